// round 16
// baseline (speedup 1.0000x reference)
#include <cuda_runtime.h>
#include <cuda_bf16.h>
#include <math.h>

// SimDiff: right[f,i] = cos(x[f,i], x[f+iv, i+1])      (i < tpf-1)
//          down [f,i] = cos(x[f,i], x[f+iv, i+width])  (i < tpf-width)
// else -1. Output: [right | down], each frames*tpf f32.
//
// Model (15 rounds): dur = L1-issued LDG bytes / ~11-12 TB/s. R14 = 2.5
// streams/token. This round: QUAD CELLS = 2.0 streams/token. With lattice
// vectors R=(1,1) (right) and D=(1,w) (down), the 2x2 cell
// {t, t+R, t+D, t+R+D} has two extra internal edges: (t+R).down = t+R+D and
// (t+D).right = t+R+D. 4 tokens -> 8 streams (4 anchors + 4 external
// targets), all internal norms shared. Cells = 2x2 blocks in (a,b) lattice
// coords over (w-1) cosets r=(i-f) mod (w-1); one warp per cell, float2
// streams, 16 accumulators. iv!=1 uses the proven R14 2-step decode.

#define EPSN 1e-8f

// ---- R14 2-step body (used by the iv!=1 fallback path) ----
template <int NPL>
__device__ __forceinline__ void body2(
    const float* __restrict__ x,
    float* __restrict__ outR, float* __restrict__ outD,
    int t0, int t1,
    int ta0, int ta1, int ta2, int tc0, int tc1,
    bool v0, bool v1, bool vr0, bool vd0, bool vr1, bool vd1,
    int lane)
{
    const int D = NPL * 128;
    const float2* __restrict__ A0 =
        reinterpret_cast<const float2*>(x + (size_t)ta0 * D) + lane;
    const float2* __restrict__ A1 =
        reinterpret_cast<const float2*>(x + (size_t)ta1 * D) + lane;
    const float2* __restrict__ A2 =
        reinterpret_cast<const float2*>(x + (size_t)ta2 * D) + lane;
    const float2* __restrict__ C0 =
        reinterpret_cast<const float2*>(x + (size_t)tc0 * D) + lane;
    const float2* __restrict__ C1 =
        reinterpret_cast<const float2*>(x + (size_t)tc1 * D) + lane;

    float n0 = 0.f, n1 = 0.f, n2 = 0.f;
    float d10 = 0.f, d11 = 0.f, d20 = 0.f, d21 = 0.f, m0 = 0.f, m1 = 0.f;

#pragma unroll
    for (int k = 0; k < 2 * NPL; k++) {
        const float2 a0 = A0[32 * k];
        const float2 a1 = A1[32 * k];
        const float2 a2 = A2[32 * k];
        const float2 c0 = C0[32 * k];
        const float2 c1 = C1[32 * k];
        n0  = fmaf(a0.x, a0.x, n0);  n0  = fmaf(a0.y, a0.y, n0);
        n1  = fmaf(a1.x, a1.x, n1);  n1  = fmaf(a1.y, a1.y, n1);
        n2  = fmaf(a2.x, a2.x, n2);  n2  = fmaf(a2.y, a2.y, n2);
        d10 = fmaf(a0.x, a1.x, d10); d10 = fmaf(a0.y, a1.y, d10);
        d11 = fmaf(a1.x, a2.x, d11); d11 = fmaf(a1.y, a2.y, d11);
        d20 = fmaf(a0.x, c0.x, d20); d20 = fmaf(a0.y, c0.y, d20);
        d21 = fmaf(a1.x, c1.x, d21); d21 = fmaf(a1.y, c1.y, d21);
        m0  = fmaf(c0.x, c0.x, m0);  m0  = fmaf(c0.y, c0.y, m0);
        m1  = fmaf(c1.x, c1.x, m1);  m1  = fmaf(c1.y, c1.y, m1);
    }

#pragma unroll
    for (int off = 16; off > 0; off >>= 1) {
        n0  += __shfl_xor_sync(0xFFFFFFFFu, n0,  off);
        n1  += __shfl_xor_sync(0xFFFFFFFFu, n1,  off);
        n2  += __shfl_xor_sync(0xFFFFFFFFu, n2,  off);
        d10 += __shfl_xor_sync(0xFFFFFFFFu, d10, off);
        d11 += __shfl_xor_sync(0xFFFFFFFFu, d11, off);
        d20 += __shfl_xor_sync(0xFFFFFFFFu, d20, off);
        d21 += __shfl_xor_sync(0xFFFFFFFFu, d21, off);
        m0  += __shfl_xor_sync(0xFFFFFFFFu, m0,  off);
        m1  += __shfl_xor_sync(0xFFFFFFFFu, m1,  off);
    }

    if (lane == 0) {
        if (v0) {
            const float nA0 = fmaxf(sqrtf(n0), EPSN);
            outR[t0] = vr0 ? d10 / (nA0 * fmaxf(sqrtf(n1), EPSN)) : -1.0f;
            outD[t0] = vd0 ? d20 / (nA0 * fmaxf(sqrtf(m0), EPSN)) : -1.0f;
        }
        if (v1) {
            const float nA1 = fmaxf(sqrtf(n1), EPSN);
            outR[t1] = vr1 ? d11 / (nA1 * fmaxf(sqrtf(n2), EPSN)) : -1.0f;
            outD[t1] = vd1 ? d21 / (nA1 * fmaxf(sqrtf(m1), EPSN)) : -1.0f;
        }
    }
}

template <int NPL>  // D = NPL * 128 floats
__global__ void __launch_bounds__(256, 4) simdiff_quad_kernel(
    const float* __restrict__ x,
    const int* __restrict__ p_frames,
    const int* __restrict__ p_height,
    const int* __restrict__ p_width,
    const int* __restrict__ p_interval,
    float* __restrict__ out,
    int total)
{
    const int width  = *p_width;
    const int height = *p_height;
    const int F      = *p_frames;
    const int iv     = *p_interval;
    const int tpf    = width * height;
    const int D      = NPL * 128;

    const int wib  = threadIdx.x >> 5;      // 0..7
    const int lane = threadIdx.x & 31;

    float* __restrict__ outR = out;
    float* __restrict__ outD = out + total;

    if (iv == 1 && width >= 2) {
        // ---- quad cells over the (R, D) lattice ----
        const int W1 = width - 1;
        const int T  = tpf;
        // b (D-coord) global range: W1*b + r in [-(F-1), T-1], r in [0,W1)
        const int b_lo = -((F + W1 - 2) / W1);
        const int b_hi = (T - 1) / W1;
        // a (R-coord) global range
        const int a_lo = -b_hi;
        const int a_hi = (F - 1) - b_lo;
        const int Bbase = b_lo >> 1, Btop = b_hi >> 1;
        const int Abase = a_lo >> 1, Atop = a_hi >> 1;
        const int NB = Btop - Bbase + 1;
        const int NA = Atop - Abase + 1;
        const long ntile = (long)W1 * NB * NA;

        const int dtok = tpf + 1;           // +R in token index
        const int ctok = tpf + width;       // +D in token index

        const long wstride = (long)gridDim.x * 8;
        const long w0 = (long)blockIdx.x * 8 + wib;

        for (long g = w0; g < ntile; g += wstride) {
            const int r  = (int)(g % W1);
            const long h = g / W1;
            const int B  = Bbase + (int)(h % NB);
            const int A  = Abase + (int)(h / NB);

            const int a0 = 2 * A, b0 = 2 * B;
            const int f00 = a0 + b0;
            const int i00 = r + a0 + width * b0;

            // Token validity (tokens: 00, 10=+R, 01=+D, 11=+R+D)
            const bool v00 = (f00 >= 0) && (f00 < F) && (i00 >= 0) && (i00 < T);
            const bool v10 = (f00 + 1 >= 0) && (f00 + 1 < F) &&
                             (i00 + 1 >= 0) && (i00 + 1 < T);
            const bool v01 = (f00 + 1 >= 0) && (f00 + 1 < F) &&
                             (i00 + width >= 0) && (i00 + width < T);
            const bool v11 = (f00 + 2 >= 0) && (f00 + 2 < F) &&
                             (i00 + width + 1 >= 0) && (i00 + width + 1 < T);
            if (!(v00 || v10 || v01 || v11)) continue;

            // Output validity per token
            const bool vr00 = v00 && (f00 + 1 < F) && (i00 + 1 < T);
            const bool vd00 = v00 && (f00 + 1 < F) && (i00 + width < T);
            const bool vr10 = v10 && (f00 + 2 < F) && (i00 + 2 < T);
            const bool vd10 = v10 && (f00 + 2 < F) && (i00 + 1 + width < T);
            const bool vr01 = v01 && (f00 + 2 < F) && (i00 + width + 1 < T);
            const bool vd01 = v01 && (f00 + 2 < F) && (i00 + 2 * width < T);
            const bool vr11 = v11 && (f00 + 3 < F) && (i00 + width + 2 < T);
            const bool vd11 = v11 && (f00 + 3 < F) && (i00 + 2 * width + 1 < T);

            // Token indices (computed from own f,i; safe arithmetic)
            const int t00 = f00 * tpf + i00;
            const int t10 = t00 + dtok;
            const int t01 = t00 + ctok;
            const int t11 = t00 + dtok + ctok;
            const int tsafe = v00 ? t00 : (v10 ? t10 : (v01 ? t01 : t11));

            // 8 streams: 4 anchors + 4 external targets (clamped if unused).
            const int s0 = v00 ? t00 : tsafe;
            const int s1 = v10 ? t10 : tsafe;
            const int s2 = v01 ? t01 : tsafe;
            const int s3 = v11 ? t11 : tsafe;
            const int s4 = vr10 ? t10 + dtok : tsafe;   // right of t10
            const int s5 = vd01 ? t01 + ctok : tsafe;   // down of t01
            const int s6 = vr11 ? t11 + dtok : tsafe;   // right of t11
            const int s7 = vd11 ? t11 + ctok : tsafe;   // down of t11

            const float2* __restrict__ P0 =
                reinterpret_cast<const float2*>(x + (size_t)s0 * D) + lane;
            const float2* __restrict__ P1 =
                reinterpret_cast<const float2*>(x + (size_t)s1 * D) + lane;
            const float2* __restrict__ P2 =
                reinterpret_cast<const float2*>(x + (size_t)s2 * D) + lane;
            const float2* __restrict__ P3 =
                reinterpret_cast<const float2*>(x + (size_t)s3 * D) + lane;
            const float2* __restrict__ P4 =
                reinterpret_cast<const float2*>(x + (size_t)s4 * D) + lane;
            const float2* __restrict__ P5 =
                reinterpret_cast<const float2*>(x + (size_t)s5 * D) + lane;
            const float2* __restrict__ P6 =
                reinterpret_cast<const float2*>(x + (size_t)s6 * D) + lane;
            const float2* __restrict__ P7 =
                reinterpret_cast<const float2*>(x + (size_t)s7 * D) + lane;

            float n0 = 0.f, n1 = 0.f, n2 = 0.f, n3 = 0.f;
            float n4 = 0.f, n5 = 0.f, n6 = 0.f, n7 = 0.f;
            float qr00 = 0.f, qd00 = 0.f, qr10 = 0.f, qd10 = 0.f;
            float qr01 = 0.f, qd01 = 0.f, qr11 = 0.f, qd11 = 0.f;

#pragma unroll
            for (int k = 0; k < 2 * NPL; k++) {
                const float2 e0 = P0[32 * k];
                const float2 e1 = P1[32 * k];
                const float2 e2 = P2[32 * k];
                const float2 e3 = P3[32 * k];
                const float2 e4 = P4[32 * k];
                const float2 e5 = P5[32 * k];
                const float2 e6 = P6[32 * k];
                const float2 e7 = P7[32 * k];
                n0 = fmaf(e0.x, e0.x, n0); n0 = fmaf(e0.y, e0.y, n0);
                n1 = fmaf(e1.x, e1.x, n1); n1 = fmaf(e1.y, e1.y, n1);
                n2 = fmaf(e2.x, e2.x, n2); n2 = fmaf(e2.y, e2.y, n2);
                n3 = fmaf(e3.x, e3.x, n3); n3 = fmaf(e3.y, e3.y, n3);
                n4 = fmaf(e4.x, e4.x, n4); n4 = fmaf(e4.y, e4.y, n4);
                n5 = fmaf(e5.x, e5.x, n5); n5 = fmaf(e5.y, e5.y, n5);
                n6 = fmaf(e6.x, e6.x, n6); n6 = fmaf(e6.y, e6.y, n6);
                n7 = fmaf(e7.x, e7.x, n7); n7 = fmaf(e7.y, e7.y, n7);
                qr00 = fmaf(e0.x, e1.x, qr00); qr00 = fmaf(e0.y, e1.y, qr00);
                qd00 = fmaf(e0.x, e2.x, qd00); qd00 = fmaf(e0.y, e2.y, qd00);
                qr10 = fmaf(e1.x, e4.x, qr10); qr10 = fmaf(e1.y, e4.y, qr10);
                qd10 = fmaf(e1.x, e3.x, qd10); qd10 = fmaf(e1.y, e3.y, qd10);
                qr01 = fmaf(e2.x, e3.x, qr01); qr01 = fmaf(e2.y, e3.y, qr01);
                qd01 = fmaf(e2.x, e5.x, qd01); qd01 = fmaf(e2.y, e5.y, qd01);
                qr11 = fmaf(e3.x, e6.x, qr11); qr11 = fmaf(e3.y, e6.y, qr11);
                qd11 = fmaf(e3.x, e7.x, qd11); qd11 = fmaf(e3.y, e7.y, qd11);
            }

#pragma unroll
            for (int off = 16; off > 0; off >>= 1) {
                n0   += __shfl_xor_sync(0xFFFFFFFFu, n0,   off);
                n1   += __shfl_xor_sync(0xFFFFFFFFu, n1,   off);
                n2   += __shfl_xor_sync(0xFFFFFFFFu, n2,   off);
                n3   += __shfl_xor_sync(0xFFFFFFFFu, n3,   off);
                n4   += __shfl_xor_sync(0xFFFFFFFFu, n4,   off);
                n5   += __shfl_xor_sync(0xFFFFFFFFu, n5,   off);
                n6   += __shfl_xor_sync(0xFFFFFFFFu, n6,   off);
                n7   += __shfl_xor_sync(0xFFFFFFFFu, n7,   off);
                qr00 += __shfl_xor_sync(0xFFFFFFFFu, qr00, off);
                qd00 += __shfl_xor_sync(0xFFFFFFFFu, qd00, off);
                qr10 += __shfl_xor_sync(0xFFFFFFFFu, qr10, off);
                qd10 += __shfl_xor_sync(0xFFFFFFFFu, qd10, off);
                qr01 += __shfl_xor_sync(0xFFFFFFFFu, qr01, off);
                qd01 += __shfl_xor_sync(0xFFFFFFFFu, qd01, off);
                qr11 += __shfl_xor_sync(0xFFFFFFFFu, qr11, off);
                qd11 += __shfl_xor_sync(0xFFFFFFFFu, qd11, off);
            }

            if (lane == 0) {
                const float r0 = fmaxf(sqrtf(n0), EPSN);
                const float r1 = fmaxf(sqrtf(n1), EPSN);
                const float r2 = fmaxf(sqrtf(n2), EPSN);
                const float r3 = fmaxf(sqrtf(n3), EPSN);
                if (v00) {
                    outR[t00] = vr00 ? qr00 / (r0 * r1) : -1.0f;
                    outD[t00] = vd00 ? qd00 / (r0 * r2) : -1.0f;
                }
                if (v10) {
                    outR[t10] = vr10 ? qr10 / (r1 * fmaxf(sqrtf(n4), EPSN)) : -1.0f;
                    outD[t10] = vd10 ? qd10 / (r1 * r3) : -1.0f;
                }
                if (v01) {
                    outR[t01] = vr01 ? qr01 / (r2 * r3) : -1.0f;
                    outD[t01] = vd01 ? qd01 / (r2 * fmaxf(sqrtf(n5), EPSN)) : -1.0f;
                }
                if (v11) {
                    outR[t11] = vr11 ? qr11 / (r3 * fmaxf(sqrtf(n6), EPSN)) : -1.0f;
                    outD[t11] = vd11 ? qd11 / (r3 * fmaxf(sqrtf(n7), EPSN)) : -1.0f;
                }
            }
        }
    } else {
        // ---- general-iv fallback: R14 lattice 2-step decode (proven) ----
        const int frames = F;
        const int nch_a = iv * tpf;
        const int nch_b = frames > iv ? frames - iv : 0;
        const int nch   = nch_a + nch_b;
        const int maxL  = min((frames + iv - 1) / iv, tpf);
        const int ncb = (nch + 1) >> 1;
        const int nsb = (maxL + 7) >> 3;
        const long ntile = (long)ncb * nsb;

        const int jj = wib & 1;
        const int kk = wib >> 1;
        const int dtok = iv * tpf + 1;
        const int ctok = iv * tpf + width;

        for (long p = blockIdx.x; p < ntile; p += gridDim.x) {
            const int cb = (int)(p % ncb);
            const int sb = (int)(p / ncb);

            const int ci = cb * 2 + jj;
            if (ci >= nch) continue;

            int f0c, i0c;
            if (ci < nch_a) { f0c = ci % iv; i0c = ci / iv; }
            else            { f0c = iv + (ci - nch_a); i0c = 0; }
            if (f0c >= frames || i0c >= tpf) continue;

            const int Lc = min((frames - f0c + iv - 1) / iv, tpf - i0c);
            const int s0 = sb * 8 + kk * 2;
            if (s0 >= Lc) continue;

            const int fA = f0c + s0 * iv;
            const int iA = i0c + s0;
            const int t0 = fA * tpf + iA;

            const bool vf0 = (fA + iv) < frames;
            const bool vr0 = vf0 && (iA + 1 < tpf);
            const bool vd0 = vf0 && (iA < tpf - width);

            const int t1  = t0 + dtok;
            const bool v1 = vr0;
            const bool vf1 = v1 && ((fA + 2 * iv) < frames);
            const bool vr1 = vf1 && (iA + 2 < tpf);
            const bool vd1 = vf1 && (iA + 1 < tpf - width);

            const int ta1 = v1  ? t1 : t0;
            const int ta2 = vr1 ? t1 + dtok : ta1;
            const int tc0 = vd0 ? t0 + ctok : t0;
            const int tc1 = vd1 ? t1 + ctok : t0;

            body2<NPL>(x, outR, outD, t0, t1, t0, ta1, ta2, tc0, tc1,
                       true, v1, vr0, vd0, vr1, vd1, lane);
        }
    }
}

// Generic fallback for arbitrary D (scalar loads, one warp per token).
__global__ void __launch_bounds__(256) simdiff_generic_kernel(
    const float* __restrict__ x,
    const int* __restrict__ p_frames,
    const int* __restrict__ p_height,
    const int* __restrict__ p_width,
    const int* __restrict__ p_interval,
    float* __restrict__ out,
    int total, int D)
{
    const int gwarp = (blockIdx.x * blockDim.x + threadIdx.x) >> 5;
    const int lane  = threadIdx.x & 31;
    if (gwarp >= total) return;

    const int width    = *p_width;
    const int height   = *p_height;
    const int frames   = *p_frames;
    const int interval = *p_interval;
    const int tpf      = width * height;

    const int f = gwarp / tpf;
    const int i = gwarp - f * tpf;

    float* __restrict__ outR = out;
    float* __restrict__ outD = out + total;

    const bool vf = (f + interval) < frames;
    if (!vf) {
        if (lane == 0) { outR[gwarp] = -1.0f; outD[gwarp] = -1.0f; }
        return;
    }
    const bool vr = (i < tpf - 1);
    const bool vd = (i < tpf - width);

    const size_t bframe = (size_t)(f + interval) * tpf + i;
    const size_t i1 = vr ? (bframe + 1)     : bframe;
    const size_t i2 = vd ? (bframe + width) : bframe;

    const float* a = x + (size_t)gwarp * D;
    const float* b = x + i1 * D;
    const float* c = x + i2 * D;

    float na = 0.0f, d1 = 0.0f, n1 = 0.0f, d2 = 0.0f, n2 = 0.0f;
    for (int k = lane; k < D; k += 32) {
        float av = a[k], bv = b[k], cv = c[k];
        na = fmaf(av, av, na);
        d1 = fmaf(av, bv, d1); n1 = fmaf(bv, bv, n1);
        d2 = fmaf(av, cv, d2); n2 = fmaf(cv, cv, n2);
    }

#pragma unroll
    for (int off = 16; off > 0; off >>= 1) {
        na += __shfl_xor_sync(0xFFFFFFFFu, na, off);
        d1 += __shfl_xor_sync(0xFFFFFFFFu, d1, off);
        n1 += __shfl_xor_sync(0xFFFFFFFFu, n1, off);
        d2 += __shfl_xor_sync(0xFFFFFFFFu, d2, off);
        n2 += __shfl_xor_sync(0xFFFFFFFFu, n2, off);
    }

    if (lane == 0) {
        const float nA = fmaxf(sqrtf(na), EPSN);
        outR[gwarp] = vr ? d1 / (nA * fmaxf(sqrtf(n1), EPSN)) : -1.0f;
        outD[gwarp] = vd ? d2 / (nA * fmaxf(sqrtf(n2), EPSN)) : -1.0f;
    }
}

extern "C" void kernel_launch(void* const* d_in, const int* in_sizes, int n_in,
                              void* d_out, int out_size) {
    const float* x        = (const float*)d_in[0];
    const int* p_frames   = (const int*)d_in[1];
    const int* p_height   = (const int*)d_in[2];
    const int* p_width    = (const int*)d_in[3];
    const int* p_interval = (const int*)d_in[4];
    float* out = (float*)d_out;

    const int total = out_size / 2;            // frames * tpf
    const int D     = in_sizes[0] / total;     // hidden dim

    if (D == 1152 || D == 1024 || D == 1280) {
        // Cells ~ total/4 * ~1.7 bounding-box bloat / 8 warps per CTA;
        // grid-stride covers any shape, dead cells exit before loads.
        const int blocks = total / 16 + 768;
        if (D == 1152) {
            simdiff_quad_kernel<9><<<blocks, 256>>>(
                x, p_frames, p_height, p_width, p_interval, out, total);
        } else if (D == 1024) {
            simdiff_quad_kernel<8><<<blocks, 256>>>(
                x, p_frames, p_height, p_width, p_interval, out, total);
        } else {
            simdiff_quad_kernel<10><<<blocks, 256>>>(
                x, p_frames, p_height, p_width, p_interval, out, total);
        }
    } else {
        const int blocks = (total + 7) / 8;
        simdiff_generic_kernel<<<blocks, 256>>>(
            x, p_frames, p_height, p_width, p_interval, out, total, D);
    }
}

// round 17
// speedup vs baseline: 1.3282x; 1.3282x over previous
#include <cuda_runtime.h>
#include <cuda_bf16.h>
#include <math.h>

// SimDiff: right[f,i] = cos(x[f,i], x[f+iv, i+1])      (i < tpf-1)
//          down [f,i] = cos(x[f,i], x[f+iv, i+width])  (i < tpf-width)
// else -1. Output: [right | down], each frames*tpf f32.
//
// R14 (2-step float2 warps, 48 regs, 40 warps/SM) = 37.3us, best. This
// round changes ONLY the chain-pairing map: a CTA pairs chains delta and
// delta+(width-1) (instead of adjacent). For iv==1 all type-a chains start
// at f0=0, so paired chains are frame-aligned and chain-A's down-target at
// step s IS chain-B's anchor at step s+1 -> down-streams merge with anchor
// streams inside the CTA. In-CTA distinct streams: 9+9+8 = 26 / 16 tokens
// (1.625x ideal L2) vs R14's ~2.125x, at identical L1-issued volume (2.5x),
// identical body, registers, and launch shape. Short type-b chains (f0>0)
// keep adjacent pairing (5.7% of work). Worst case == R14.

#define EPSN 1e-8f

// 2-step warp body: 5 float2 streams, 9 accumulators, norm chain via n1.
template <int NPL>
__device__ __forceinline__ void body2(
    const float* __restrict__ x,
    float* __restrict__ outR, float* __restrict__ outD,
    int t0, int t1,
    int ta1, int ta2, int tc0, int tc1,
    bool v1, bool vr0, bool vd0, bool vr1, bool vd1,
    int lane)
{
    const int D = NPL * 128;
    const float2* __restrict__ A0 =
        reinterpret_cast<const float2*>(x + (size_t)t0 * D) + lane;
    const float2* __restrict__ A1 =
        reinterpret_cast<const float2*>(x + (size_t)ta1 * D) + lane;
    const float2* __restrict__ A2 =
        reinterpret_cast<const float2*>(x + (size_t)ta2 * D) + lane;
    const float2* __restrict__ C0 =
        reinterpret_cast<const float2*>(x + (size_t)tc0 * D) + lane;
    const float2* __restrict__ C1 =
        reinterpret_cast<const float2*>(x + (size_t)tc1 * D) + lane;

    float n0 = 0.f, n1 = 0.f, n2 = 0.f;          // |a0|^2 |a1|^2 |a2|^2
    float d10 = 0.f, d11 = 0.f;                  // a0.a1, a1.a2
    float d20 = 0.f, d21 = 0.f;                  // a0.c0, a1.c1
    float m0 = 0.f, m1 = 0.f;                    // |c0|^2, |c1|^2

#pragma unroll
    for (int k = 0; k < 2 * NPL; k++) {
        const float2 a0 = A0[32 * k];
        const float2 a1 = A1[32 * k];
        const float2 a2 = A2[32 * k];
        const float2 c0 = C0[32 * k];
        const float2 c1 = C1[32 * k];
        n0  = fmaf(a0.x, a0.x, n0);  n0  = fmaf(a0.y, a0.y, n0);
        n1  = fmaf(a1.x, a1.x, n1);  n1  = fmaf(a1.y, a1.y, n1);
        n2  = fmaf(a2.x, a2.x, n2);  n2  = fmaf(a2.y, a2.y, n2);
        d10 = fmaf(a0.x, a1.x, d10); d10 = fmaf(a0.y, a1.y, d10);
        d11 = fmaf(a1.x, a2.x, d11); d11 = fmaf(a1.y, a2.y, d11);
        d20 = fmaf(a0.x, c0.x, d20); d20 = fmaf(a0.y, c0.y, d20);
        d21 = fmaf(a1.x, c1.x, d21); d21 = fmaf(a1.y, c1.y, d21);
        m0  = fmaf(c0.x, c0.x, m0);  m0  = fmaf(c0.y, c0.y, m0);
        m1  = fmaf(c1.x, c1.x, m1);  m1  = fmaf(c1.y, c1.y, m1);
    }

#pragma unroll
    for (int off = 16; off > 0; off >>= 1) {
        n0  += __shfl_xor_sync(0xFFFFFFFFu, n0,  off);
        n1  += __shfl_xor_sync(0xFFFFFFFFu, n1,  off);
        n2  += __shfl_xor_sync(0xFFFFFFFFu, n2,  off);
        d10 += __shfl_xor_sync(0xFFFFFFFFu, d10, off);
        d11 += __shfl_xor_sync(0xFFFFFFFFu, d11, off);
        d20 += __shfl_xor_sync(0xFFFFFFFFu, d20, off);
        d21 += __shfl_xor_sync(0xFFFFFFFFu, d21, off);
        m0  += __shfl_xor_sync(0xFFFFFFFFu, m0,  off);
        m1  += __shfl_xor_sync(0xFFFFFFFFu, m1,  off);
    }

    if (lane == 0) {
        const float nA0 = fmaxf(sqrtf(n0), EPSN);
        outR[t0] = vr0 ? d10 / (nA0 * fmaxf(sqrtf(n1), EPSN)) : -1.0f;
        outD[t0] = vd0 ? d20 / (nA0 * fmaxf(sqrtf(m0), EPSN)) : -1.0f;
        if (v1) {   // token 1 exists exactly when vr0
            const float nA1 = fmaxf(sqrtf(n1), EPSN);
            outR[t1] = vr1 ? d11 / (nA1 * fmaxf(sqrtf(n2), EPSN)) : -1.0f;
            outD[t1] = vd1 ? d21 / (nA1 * fmaxf(sqrtf(m1), EPSN)) : -1.0f;
        }
    }
}

template <int NPL>  // D = NPL * 128 floats
__global__ void __launch_bounds__(256, 5) simdiff_wpair_kernel(
    const float* __restrict__ x,
    const int* __restrict__ p_frames,
    const int* __restrict__ p_height,
    const int* __restrict__ p_width,
    const int* __restrict__ p_interval,
    float* __restrict__ out,
    int total)
{
    const int width  = *p_width;
    const int height = *p_height;
    const int frames = *p_frames;
    const int iv     = *p_interval;
    const int tpf    = width * height;

    // Diagonal chains: step (f += iv, i += 1). Starts: f0 < iv (any i0),
    // or i0 == 0 (f0 in [iv, frames)). Every token on exactly one chain.
    const int nch_a = iv * tpf;
    const int nch_b = frames > iv ? frames - iv : 0;
    const int nch   = nch_a + nch_b;
    const int maxL  = min((frames + iv - 1) / iv, tpf);

    // CTA tile: 2 chains x 4 warp-slots x 2 steps each = 8 steps per chain.
    const int ncb = (nch + 1) >> 1;
    const int nsb = (maxL + 7) >> 3;
    const long ntile = (long)ncb * nsb;

    // Width-pairing parameters (iv==1): pair chain delta with delta+W1 among
    // the frame-aligned type-a chains (f0 == 0). na_p = A-chains in complete
    // 2*W1 groups. Remainder chains (type-a leftovers + type-b) pair
    // adjacently as in R14.
    const int W1 = width - 1;
    const bool wp = (iv == 1) && (width >= 2);
    const int na_p = wp ? (tpf / (2 * W1)) * W1 : 0;

    const int wib  = threadIdx.x >> 5;      // 0..7
    const int lane = threadIdx.x & 31;
    const int jj   = wib & 1;               // chain in tile (A=0 / B=1)
    const int kk   = wib >> 1;              // step-pair slot (0..3)

    float* __restrict__ outR = out;
    float* __restrict__ outD = out + total;
    const int dtok = iv * tpf + 1;          // chain step token offset
    const int ctok = iv * tpf + width;      // down-target token offset

    for (long p = blockIdx.x; p < ntile; p += gridDim.x) {
        const int cb = (int)(p % ncb);
        const int sb = (int)(p / ncb);

        int ci;
        if (wp && cb < na_p) {
            const int g = cb / W1;
            const int r = cb - g * W1;
            ci = g * 2 * W1 + r + jj * W1;   // paired: delta, delta+W1
        } else if (wp) {
            ci = 2 * na_p + (cb - na_p) * 2 + jj;
        } else {
            ci = cb * 2 + jj;
        }
        if (ci >= nch) continue;

        int f0c, i0c;
        if (ci < nch_a) { f0c = ci % iv; i0c = ci / iv; }
        else            { f0c = iv + (ci - nch_a); i0c = 0; }
        if (f0c >= frames || i0c >= tpf) continue;

        const int Lc = min((frames - f0c + iv - 1) / iv, tpf - i0c);
        const int s0 = sb * 8 + kk * 2;
        if (s0 >= Lc) continue;

        const int fA = f0c + s0 * iv;
        const int iA = i0c + s0;
        const int t0 = fA * tpf + iA;

        // Token 0 validity; token 1 exists iff vr0 (right-target on-chain).
        const bool vf0 = (fA + iv) < frames;
        const bool vr0 = vf0 && (iA + 1 < tpf);
        const bool vd0 = vf0 && (iA < tpf - width);

        const int t1  = t0 + dtok;
        const bool v1 = vr0;
        const bool vf1 = v1 && ((fA + 2 * iv) < frames);
        const bool vr1 = vf1 && (iA + 2 < tpf);
        const bool vd1 = vf1 && (iA + 1 < tpf - width);

        // Clamped stream tokens (all in-bounds; bogus results discarded).
        const int ta1 = v1  ? t1 : t0;
        const int ta2 = vr1 ? t1 + dtok : ta1;
        const int tc0 = vd0 ? t0 + ctok : t0;
        const int tc1 = vd1 ? t1 + ctok : t0;

        body2<NPL>(x, outR, outD, t0, t1, ta1, ta2, tc0, tc1,
                   v1, vr0, vd0, vr1, vd1, lane);
    }
}

// Generic fallback for arbitrary D (scalar loads, one warp per token).
__global__ void __launch_bounds__(256) simdiff_generic_kernel(
    const float* __restrict__ x,
    const int* __restrict__ p_frames,
    const int* __restrict__ p_height,
    const int* __restrict__ p_width,
    const int* __restrict__ p_interval,
    float* __restrict__ out,
    int total, int D)
{
    const int gwarp = (blockIdx.x * blockDim.x + threadIdx.x) >> 5;
    const int lane  = threadIdx.x & 31;
    if (gwarp >= total) return;

    const int width    = *p_width;
    const int height   = *p_height;
    const int frames   = *p_frames;
    const int interval = *p_interval;
    const int tpf      = width * height;

    const int f = gwarp / tpf;
    const int i = gwarp - f * tpf;

    float* __restrict__ outR = out;
    float* __restrict__ outD = out + total;

    const bool vf = (f + interval) < frames;
    if (!vf) {
        if (lane == 0) { outR[gwarp] = -1.0f; outD[gwarp] = -1.0f; }
        return;
    }
    const bool vr = (i < tpf - 1);
    const bool vd = (i < tpf - width);

    const size_t bframe = (size_t)(f + interval) * tpf + i;
    const size_t i1 = vr ? (bframe + 1)     : bframe;
    const size_t i2 = vd ? (bframe + width) : bframe;

    const float* a = x + (size_t)gwarp * D;
    const float* b = x + i1 * D;
    const float* c = x + i2 * D;

    float na = 0.0f, d1 = 0.0f, n1 = 0.0f, d2 = 0.0f, n2 = 0.0f;
    for (int k = lane; k < D; k += 32) {
        float av = a[k], bv = b[k], cv = c[k];
        na = fmaf(av, av, na);
        d1 = fmaf(av, bv, d1); n1 = fmaf(bv, bv, n1);
        d2 = fmaf(av, cv, d2); n2 = fmaf(cv, cv, n2);
    }

#pragma unroll
    for (int off = 16; off > 0; off >>= 1) {
        na += __shfl_xor_sync(0xFFFFFFFFu, na, off);
        d1 += __shfl_xor_sync(0xFFFFFFFFu, d1, off);
        n1 += __shfl_xor_sync(0xFFFFFFFFu, n1, off);
        d2 += __shfl_xor_sync(0xFFFFFFFFu, d2, off);
        n2 += __shfl_xor_sync(0xFFFFFFFFu, n2, off);
    }

    if (lane == 0) {
        const float nA = fmaxf(sqrtf(na), EPSN);
        outR[gwarp] = vr ? d1 / (nA * fmaxf(sqrtf(n1), EPSN)) : -1.0f;
        outD[gwarp] = vd ? d2 / (nA * fmaxf(sqrtf(n2), EPSN)) : -1.0f;
    }
}

extern "C" void kernel_launch(void* const* d_in, const int* in_sizes, int n_in,
                              void* d_out, int out_size) {
    const float* x        = (const float*)d_in[0];
    const int* p_frames   = (const int*)d_in[1];
    const int* p_height   = (const int*)d_in[2];
    const int* p_width    = (const int*)d_in[3];
    const int* p_interval = (const int*)d_in[4];
    float* out = (float*)d_out;

    const int total = out_size / 2;            // frames * tpf
    const int D     = in_sizes[0] / total;     // hidden dim

    if (D == 1152 || D == 1024 || D == 1280) {
        // ~total/16 useful tiles (16 tokens per CTA) + chain-edge padding;
        // grid-stride covers any shape, surplus tiles exit immediately.
        const int blocks = total / 16 + 1024;
        if (D == 1152) {
            simdiff_wpair_kernel<9><<<blocks, 256>>>(
                x, p_frames, p_height, p_width, p_interval, out, total);
        } else if (D == 1024) {
            simdiff_wpair_kernel<8><<<blocks, 256>>>(
                x, p_frames, p_height, p_width, p_interval, out, total);
        } else {
            simdiff_wpair_kernel<10><<<blocks, 256>>>(
                x, p_frames, p_height, p_width, p_interval, out, total);
        }
    } else {
        const int blocks = (total + 7) / 8;
        simdiff_generic_kernel<<<blocks, 256>>>(
            x, p_frames, p_height, p_width, p_interval, out, total, D);
    }
}